// round 11
// baseline (speedup 1.0000x reference)
#include <cuda_runtime.h>
#include <cuda_bf16.h>
#include <math.h>

// ConvLSTM via mma.sync m16n8k16 bf16, 3-term hi/lo split.
// Round 11: (a) compact A smem layout [sp][k-half][pixel][8] (16B units,
// conflict-free LDSM, 25.3KB); (b) weights double-buffered (2x38.9KB) and
// prefetched behind the tap loop -> only input staging exposed;
// (c) kb order staggered by CTA parity to decorrelate resident CTAs.
// CTA = 256 px (4 rows x 64) x 64 oc, 8 warps, 2 m-tiles/warp, regs<=128,
// smem 103.2KB -> 2 CTAs/SM.
// x: (8,16,64,64,64) f32, Wk: (256,128,3,3) f32
// out: [hid | cell], each 8*64*64*64 f32 (NCHW).

#define HW 64

__device__ __nv_bfloat16 g_xs[2][8][16][HW][HW][64];   // x channel-last hi/lo
__device__ __nv_bfloat16 g_hs[2][2][8][HW][HW][64];    // [parity][split] h hi/lo
__device__ __nv_bfloat16 g_wpk[4][8][19456];           // packed weights (hcg,kb)
__device__ __align__(16) __nv_bfloat16 g_zero16[8] = {};

// smem (bf16 elems):
//   input  [sp2][half2][pix 396][8] = 12672   (25344 B, single buffer)
//   weights[sp2][ocl 64][152]       = 19456   (38912 B, DOUBLE buffer)
#define SIN_ELEMS   12672
#define SIN_SP      6336            // elems per sp plane
#define SIN_HALF    3168            // elems per k-half plane
#define WBUF_ELEMS  19456
#define W_SP        (64 * 152)
#define SMEM_BYTES  ((12672 + 2 * 19456) * 2)   // 103168 B

// ---------------- prep kernels ----------------

__global__ void prep_x(const float* __restrict__ x)
{
    __shared__ float tile[64][65];
    int y  = blockIdx.x & 63;
    int bt = blockIdx.x >> 6;               // b*16 + t
    const float* src = x + (size_t)bt * 64 * 4096 + y * 64;
    for (int i = threadIdx.x; i < 64 * 64; i += 256) {
        int ic = i >> 6, xx = i & 63;
        tile[ic][xx] = src[ic * 4096 + xx];
    }
    __syncthreads();
    int b = bt >> 4, t = bt & 15;
    for (int i = threadIdx.x; i < 64 * 64; i += 256) {
        int xx = i >> 6, ic = i & 63;
        float v = tile[ic][xx];
        __nv_bfloat16 hi = __float2bfloat16(v);
        g_xs[0][b][t][y][xx][ic] = hi;
        g_xs[1][b][t][y][xx][ic] = __float2bfloat16(v - __bfloat162float(hi));
    }
}

// Pack weights for (hcg,kb): [sp][ocl 64][k 152], k = tap*16+ic (144 valid).
__global__ void prep_wpk(const float* __restrict__ Wk)
{
    int i = blockIdx.x * blockDim.x + threadIdx.x;  // over 4*8*19456
    if (i >= 4 * 8 * 19456) return;
    int e   = i % 19456;
    int kb  = (i / 19456) & 7;
    int hcg = i / (19456 * 8);
    int sp  = e / 9728;
    int r   = e - sp * 9728;
    int ocl = r / 152;
    int kk  = r - ocl * 152;
    __nv_bfloat16 out = __float2bfloat16(0.f);
    if (kk < 144) {
        int tap = kk >> 4, ic = kk & 15;
        int oc  = (ocl >> 4) * 64 + hcg * 16 + (ocl & 15);
        int cin = kb * 16 + ic;
        float v = Wk[(size_t)(oc * 128 + cin) * 9 + tap];
        __nv_bfloat16 hi = __float2bfloat16(v);
        out = sp ? __float2bfloat16(v - __bfloat162float(hi)) : hi;
    }
    g_wpk[hcg][kb][e] = out;
}

// ---------------- helpers ----------------

__device__ __forceinline__ void ldsm4(unsigned &r0, unsigned &r1,
                                      unsigned &r2, unsigned &r3, unsigned a)
{
    asm volatile("ldmatrix.sync.aligned.m8n8.x4.shared.b16 {%0,%1,%2,%3}, [%4];"
                 : "=r"(r0), "=r"(r1), "=r"(r2), "=r"(r3) : "r"(a));
}

__device__ __forceinline__ void mma_bf16(float* c, const unsigned* a, const unsigned* b)
{
    asm volatile("mma.sync.aligned.m16n8k16.row.col.f32.bf16.bf16.f32 "
                 "{%0,%1,%2,%3},{%4,%5,%6,%7},{%8,%9},{%0,%1,%2,%3};"
                 : "+f"(c[0]), "+f"(c[1]), "+f"(c[2]), "+f"(c[3])
                 : "r"(a[0]), "r"(a[1]), "r"(a[2]), "r"(a[3]),
                   "r"(b[0]), "r"(b[1]));
}

__device__ __forceinline__ void cpasync16(unsigned dst, const void* src)
{
    asm volatile("cp.async.cg.shared.global [%0], [%1], 16;"
                 :: "r"(dst), "l"(src) : "memory");
}

__global__ __launch_bounds__(256, 2)
void convlstm_mma(float* __restrict__ hid_out, float* __restrict__ cell_io,
                  int t, int last)
{
    extern __shared__ __nv_bfloat16 smem[];
    // [input][w buf0][w buf1]
    const unsigned sIn = (unsigned)__cvta_generic_to_shared(smem);
    const unsigned sW0 = sIn + SIN_ELEMS * 2;
    const unsigned sW1 = sW0 + WBUF_ELEMS * 2;

    const int tid  = threadIdx.x;
    const int w    = tid >> 5;            // 0..7
    const int lane = tid & 31;
    const int y0   = blockIdx.x * 4;      // 4 output rows per block
    const int hcg  = blockIdx.y;
    const int b    = blockIdx.z;

    const int par_in  = t & 1;
    const int par_out = (t + 1) & 1;

    // lane-invariant ldmatrix offsets
    const int t4 = lane >> 3, r8 = lane & 7;
    const int prA = ((t4 & 1) << 3) + r8;      // row within m16
    const int k8A = t4 >> 1;                   // k-half
    unsigned laneA[2];
#pragma unroll
    for (int mt = 0; mt < 2; mt++) {
        const int p0  = w * 32 + mt * 16 + prA;   // 0..255
        const int pyA = p0 >> 6;
        const int pxA = p0 & 63;
        laneA[mt] = (unsigned)(k8A * SIN_HALF + (pyA * 66 + pxA) * 8) * 2u;
    }
    const int hi8 = (t4 >= 2) ? 8 : 0;
    const unsigned laneB = (unsigned)((hi8 + r8) * 152 + 8 * (t4 & 1)) * 2u;

    float acc[2][8][4];
#pragma unroll
    for (int m = 0; m < 2; m++)
#pragma unroll
        for (int i = 0; i < 8; i++)
#pragma unroll
            for (int j = 0; j < 4; j++) acc[m][i][j] = 0.f;

    const int nkb = (t == 0) ? 4 : 8;
    // stagger kb order between resident CTA pairs (accumulation order is
    // permutation-invariant up to fp32 rounding)
    const int off = (blockIdx.x & 1) * (nkb >> 1);

    // ---- input stage loader (cp.async; caller commits) ----
    auto load_input = [&](int kb) {
        for (int c = tid; c < 1584; c += 256) {
            int sp  = c / 792;
            int r   = c - sp * 792;
            int hf  = r / 396;
            int pix = r - hf * 396;
            int sy  = pix / 66, sx = pix - sy * 66;
            int gy  = y0 - 1 + sy, gx = sx - 1;
            const void* src = g_zero16;
            if ((unsigned)gy < 64u && (unsigned)gx < 64u)
                src = (kb < 4)
                    ? (const void*)&g_xs[sp][b][t][gy][gx][kb * 16 + hf * 8]
                    : (const void*)&g_hs[par_in][sp][b][gy][gx][(kb - 4) * 16 + hf * 8];
            unsigned dst = sIn + (unsigned)((sp * 2 + hf) * 396 + pix) * 16u;
            cpasync16(dst, src);
        }
    };
    // ---- weight stage loader (contiguous 2432 x 16B; caller commits) ----
    auto load_weights = [&](int kb, unsigned sW) {
        const char* wsrc = (const char*)g_wpk[hcg][kb];
        for (int i = tid; i < 2432; i += 256)
            cpasync16(sW + (unsigned)i * 16u, wsrc + (size_t)i * 16);
    };

    // prologue: prefetch weights(seq[0]) into buf0
    load_weights(off, sW0);
    asm volatile("cp.async.commit_group;" ::: "memory");

    for (int j = 0; j < nkb; j++) {
        const int kb = (j + off) & (nkb - 1);
        if (j > 0) __syncthreads();   // all warps done with input & old w buf

        load_input(kb);
        asm volatile("cp.async.commit_group;" ::: "memory");

        if (j + 1 < nkb) {
            load_weights((j + 1 + off) & (nkb - 1), ((j + 1) & 1) ? sW1 : sW0);
            asm volatile("cp.async.commit_group;" ::: "memory");
            asm volatile("cp.async.wait_group 1;" ::: "memory");
        } else {
            asm volatile("cp.async.wait_group 0;" ::: "memory");
        }
        __syncthreads();

        const unsigned sW = (j & 1) ? sW1 : sW0;

#pragma unroll 1
        for (int tap = 0; tap < 9; tap++) {
            const int dyp = tap / 3, dxp = tap - dyp * 3;
            const unsigned aoff = (unsigned)(dyp * 66 + dxp) * 16u;
            const unsigned woff = (unsigned)(tap * 16) * 2u;

            unsigned a[2][2][4];   // [mt][sp][frag]
#pragma unroll
            for (int mt = 0; mt < 2; mt++) {
                ldsm4(a[mt][0][0], a[mt][0][1], a[mt][0][2], a[mt][0][3],
                      sIn + aoff + laneA[mt]);
                ldsm4(a[mt][1][0], a[mt][1][1], a[mt][1][2], a[mt][1][3],
                      sIn + (unsigned)(SIN_SP * 2) + aoff + laneA[mt]);
            }

            unsigned bf[8][2];
            // phase 1: B = w_hi (terms Ah*Bh, Al*Bh)
            {
                unsigned base = sW + woff + laneB;
#pragma unroll
                for (int jj = 0; jj < 4; jj++)
                    ldsm4(bf[2 * jj][0], bf[2 * jj][1],
                          bf[2 * jj + 1][0], bf[2 * jj + 1][1],
                          base + (unsigned)(16 * jj * 152) * 2u);
#pragma unroll
                for (int nf = 0; nf < 8; nf++)
#pragma unroll
                    for (int mt = 0; mt < 2; mt++) {
                        mma_bf16(acc[mt][nf], a[mt][0], bf[nf]);
                        mma_bf16(acc[mt][nf], a[mt][1], bf[nf]);
                    }
            }
            // phase 2: B = w_lo (term Ah*Bl)
            {
                unsigned base = sW + (unsigned)(W_SP * 2) + woff + laneB;
#pragma unroll
                for (int jj = 0; jj < 4; jj++)
                    ldsm4(bf[2 * jj][0], bf[2 * jj][1],
                          bf[2 * jj + 1][0], bf[2 * jj + 1][1],
                          base + (unsigned)(16 * jj * 152) * 2u);
#pragma unroll
                for (int nf = 0; nf < 8; nf++)
#pragma unroll
                    for (int mt = 0; mt < 2; mt++)
                        mma_bf16(acc[mt][nf], a[mt][0], bf[nf]);
            }
        }
    }

    // ---- fused LSTM epilogue ----
    const int c0    = (lane & 3) * 2;
    const int rbase = lane >> 2;
#pragma unroll
    for (int mt = 0; mt < 2; mt++) {
#pragma unroll
        for (int rr = 0; rr < 2; rr++) {
            const int pe = w * 32 + mt * 16 + rbase + 8 * rr;
            const int y  = y0 + (pe >> 6);
            const int x  = pe & 63;
#pragma unroll
            for (int q = 0; q < 4; q++) {
                const int hcl  = c0 + (q & 1) + ((q >> 1) << 3);
                const int off2 = (hcl >= 8) ? 1 : 0;
                const int cidx = (hcl & 7) - c0 + rr * 2;
                float vi = acc[mt][0 + off2][cidx];
                float vf = acc[mt][2 + off2][cidx];
                float vo = acc[mt][4 + off2][cidx];
                float vg = acc[mt][6 + off2][cidx];
                float iv = 1.f / (1.f + __expf(-vi));
                float fv = 1.f / (1.f + __expf(-vf));
                float ov = 1.f / (1.f + __expf(-vo));
                float gv = tanhf(vg);
                const int hc = hcg * 16 + hcl;
                const size_t addr = (((size_t)b * 64 + hc) * 64 + y) * 64 + x;
                float cold = (t == 0) ? 0.f : cell_io[addr];
                float cnew = fv * cold + iv * gv;
                cell_io[addr] = cnew;
                float hval = ov * tanhf(cnew);
                if (last) {
                    hid_out[addr] = hval;
                } else {
                    __nv_bfloat16 hh = __float2bfloat16(hval);
                    g_hs[par_out][0][b][y][x][hc] = hh;
                    g_hs[par_out][1][b][y][x][hc] =
                        __float2bfloat16(hval - __bfloat162float(hh));
                }
            }
        }
    }
}

extern "C" void kernel_launch(void* const* d_in, const int* in_sizes, int n_in,
                              void* d_out, int out_size)
{
    const float* x  = (const float*)d_in[0];
    const float* Wk = (const float*)d_in[1];
    float* out  = (float*)d_out;
    float* hid  = out;
    float* cell = out + out_size / 2;

    cudaFuncSetAttribute(convlstm_mma,
                         cudaFuncAttributeMaxDynamicSharedMemorySize, SMEM_BYTES);

    prep_wpk<<<(4 * 8 * 19456 + 255) / 256, 256>>>(Wk);
    prep_x<<<8 * 16 * 64, 256>>>(x);

    dim3 grid(16, 4, 8), blk(256);
    for (int t = 0; t < 16; t++)
        convlstm_mma<<<grid, blk, SMEM_BYTES>>>(hid, cell, t, t == 15 ? 1 : 0);
}

// round 12
// speedup vs baseline: 1.2442x; 1.2442x over previous
#include <cuda_runtime.h>
#include <cuda_bf16.h>
#include <math.h>

// ConvLSTM, mma.sync m16n8k16 bf16 3-term split, STEP-SPLIT version.
// conv(cat(x,h)) = conv_x(x) + conv_h(h). Kernel A(t) computes conv_x(x_t)
// (h-independent!) into a per-step fp32 partial buffer; kernel B(t) loads
// the partial, adds conv_h(h_{t-1}), runs the fused LSTM epilogue.
// All A's run on a low-priority concurrent stream; the serial chain is only
// B(0)->B(1)->...->B(15), each half the MACs of a full step. A-work fills
// the B-chain's idle slots (wave tail, staging gaps).
// x: (8,16,64,64,64) f32, Wk: (256,128,3,3) f32
// out: [hid | cell], each 8*64*64*64 f32 (NCHW).

#define HW 64

__device__ __nv_bfloat16 g_xs[2][8][16][HW][HW][64];   // x channel-last hi/lo
__device__ __nv_bfloat16 g_hs[2][2][8][HW][HW][64];    // [parity][split] h hi/lo
__device__ __nv_bfloat16 g_wpk[4][8][19456];           // packed weights (hcg,kb)
__device__ __align__(16) __nv_bfloat16 g_zero16[8] = {};
__device__ float4 g_part[16][2097152];                 // per-step conv_x partial

// smem (bf16 elems): in buf = [sp2][sy6][sx66][24] = 19008 (x2 buffers)
//                    w  buf = [sp2][ocl64][152]   = 19456
#define INBUF_ELEMS 19008
#define SIN_SP      (6 * 66 * 24)
#define W_SP        (64 * 152)
#define SMEM_BYTES  ((2 * 19008 + 19456) * 2)   // 114944

// ---------------- prep kernels ----------------

__global__ void prep_x(const float* __restrict__ x)
{
    __shared__ float tile[64][65];
    int y  = blockIdx.x & 63;
    int bt = blockIdx.x >> 6;               // b*16 + t
    const float* src = x + (size_t)bt * 64 * 4096 + y * 64;
    for (int i = threadIdx.x; i < 64 * 64; i += 256) {
        int ic = i >> 6, xx = i & 63;
        tile[ic][xx] = src[ic * 4096 + xx];
    }
    __syncthreads();
    int b = bt >> 4, t = bt & 15;
    for (int i = threadIdx.x; i < 64 * 64; i += 256) {
        int xx = i >> 6, ic = i & 63;
        float v = tile[ic][xx];
        __nv_bfloat16 hi = __float2bfloat16(v);
        g_xs[0][b][t][y][xx][ic] = hi;
        g_xs[1][b][t][y][xx][ic] = __float2bfloat16(v - __bfloat162float(hi));
    }
}

__global__ void prep_wpk(const float* __restrict__ Wk)
{
    int i = blockIdx.x * blockDim.x + threadIdx.x;  // over 4*8*19456
    if (i >= 4 * 8 * 19456) return;
    int e   = i % 19456;
    int kb  = (i / 19456) & 7;
    int hcg = i / (19456 * 8);
    int sp  = e / 9728;
    int r   = e - sp * 9728;
    int ocl = r / 152;
    int kk  = r - ocl * 152;
    __nv_bfloat16 out = __float2bfloat16(0.f);
    if (kk < 144) {
        int tap = kk >> 4, ic = kk & 15;
        int oc  = (ocl >> 4) * 64 + hcg * 16 + (ocl & 15);
        int cin = kb * 16 + ic;
        float v = Wk[(size_t)(oc * 128 + cin) * 9 + tap];
        __nv_bfloat16 hi = __float2bfloat16(v);
        out = sp ? __float2bfloat16(v - __bfloat162float(hi)) : hi;
    }
    g_wpk[hcg][kb][e] = out;
}

// ---------------- helpers ----------------

__device__ __forceinline__ void ldsm4(unsigned &r0, unsigned &r1,
                                      unsigned &r2, unsigned &r3, unsigned a)
{
    asm volatile("ldmatrix.sync.aligned.m8n8.x4.shared.b16 {%0,%1,%2,%3}, [%4];"
                 : "=r"(r0), "=r"(r1), "=r"(r2), "=r"(r3) : "r"(a));
}

__device__ __forceinline__ void mma_bf16(float* c, const unsigned* a, const unsigned* b)
{
    asm volatile("mma.sync.aligned.m16n8k16.row.col.f32.bf16.bf16.f32 "
                 "{%0,%1,%2,%3},{%4,%5,%6,%7},{%8,%9},{%0,%1,%2,%3};"
                 : "+f"(c[0]), "+f"(c[1]), "+f"(c[2]), "+f"(c[3])
                 : "r"(a[0]), "r"(a[1]), "r"(a[2]), "r"(a[3]),
                   "r"(b[0]), "r"(b[1]));
}

__device__ __forceinline__ void cpasync16(unsigned dst, const void* src)
{
    asm volatile("cp.async.cg.shared.global [%0], [%1], 16;"
                 :: "r"(dst), "l"(src) : "memory");
}

// Shared mainloop over 4 kb blocks. Macro-style via template flag.
// HSRC=0: read g_xs (uses t); HSRC=1: read g_hs[par_in].
template <int HSRC>
__device__ __forceinline__ void conv_half(
    float acc[2][8][4], int t, int y0, int hcg, int b,
    int w, int lane, int tid, const unsigned sIn0, const unsigned sIn1,
    const unsigned sW, const unsigned* laneA, unsigned laneB)
{
    const int par_in = t & 1;
    const int wkbase = HSRC ? 4 : 0;

    auto load_input = [&](int kb, unsigned sIn) {
        for (int c = tid; c < 1584; c += 256) {
            int sp   = c / 792;
            int idx  = c - sp * 792;
            int pix  = idx >> 1, half = idx & 1;
            int sy   = pix / 66, sx = pix - sy * 66;
            int gy   = y0 - 1 + sy, gx = sx - 1;
            const void* src = g_zero16;
            if ((unsigned)gy < 64u && (unsigned)gx < 64u)
                src = HSRC
                    ? (const void*)&g_hs[par_in][sp][b][gy][gx][kb * 16 + half * 8]
                    : (const void*)&g_xs[sp][b][t][gy][gx][kb * 16 + half * 8];
            unsigned dst = sIn + (unsigned)(((sp * 6 + sy) * 66 + sx) * 24 + half * 8) * 2u;
            cpasync16(dst, src);
        }
    };

    load_input(0, sIn0);
    asm volatile("cp.async.commit_group;" ::: "memory");

    for (int kb = 0; kb < 4; kb++) {
        if (kb > 0) __syncthreads();

        {   // stage weights(kb)
            const char* wsrc = (const char*)g_wpk[hcg][wkbase + kb];
            for (int i = tid; i < 2432; i += 256)
                cpasync16(sW + (unsigned)i * 16u, wsrc + (size_t)i * 16);
        }
        asm volatile("cp.async.commit_group;" ::: "memory");

        if (kb + 1 < 4) {
            load_input(kb + 1, (kb + 1) & 1 ? sIn1 : sIn0);
            asm volatile("cp.async.commit_group;" ::: "memory");
            asm volatile("cp.async.wait_group 1;" ::: "memory");
        } else {
            asm volatile("cp.async.wait_group 0;" ::: "memory");
        }
        __syncthreads();

        const unsigned sIn = (kb & 1) ? sIn1 : sIn0;

#pragma unroll 1
        for (int tap = 0; tap < 9; tap++) {
            const int dyp = tap / 3, dxp = tap - dyp * 3;
            const unsigned aoff = (unsigned)((dyp * 66 + dxp) * 24) * 2u;
            const unsigned woff = (unsigned)(tap * 16) * 2u;

            unsigned a[2][2][4];
#pragma unroll
            for (int mt = 0; mt < 2; mt++) {
                ldsm4(a[mt][0][0], a[mt][0][1], a[mt][0][2], a[mt][0][3],
                      sIn + aoff + laneA[mt]);
                ldsm4(a[mt][1][0], a[mt][1][1], a[mt][1][2], a[mt][1][3],
                      sIn + (unsigned)(SIN_SP * 2) + aoff + laneA[mt]);
            }

            unsigned bf[8][2];
            {   // phase 1: B = w_hi
                unsigned base = sW + woff + laneB;
#pragma unroll
                for (int j = 0; j < 4; j++)
                    ldsm4(bf[2 * j][0], bf[2 * j][1],
                          bf[2 * j + 1][0], bf[2 * j + 1][1],
                          base + (unsigned)(16 * j * 152) * 2u);
#pragma unroll
                for (int nf = 0; nf < 8; nf++)
#pragma unroll
                    for (int mt = 0; mt < 2; mt++) {
                        mma_bf16(acc[mt][nf], a[mt][0], bf[nf]);
                        mma_bf16(acc[mt][nf], a[mt][1], bf[nf]);
                    }
            }
            {   // phase 2: B = w_lo
                unsigned base = sW + (unsigned)(W_SP * 2) + woff + laneB;
#pragma unroll
                for (int j = 0; j < 4; j++)
                    ldsm4(bf[2 * j][0], bf[2 * j][1],
                          bf[2 * j + 1][0], bf[2 * j + 1][1],
                          base + (unsigned)(16 * j * 152) * 2u);
#pragma unroll
                for (int nf = 0; nf < 8; nf++)
#pragma unroll
                    for (int mt = 0; mt < 2; mt++)
                        mma_bf16(acc[mt][nf], a[mt][0], bf[nf]);
            }
        }
    }
}

__device__ __forceinline__ void lane_setup(int w, int lane,
                                           unsigned* laneA, unsigned& laneB)
{
    const int t4 = lane >> 3, r8 = lane & 7;
    const int prA = ((t4 & 1) << 3) + r8;
    const int k8A = t4 >> 1;
#pragma unroll
    for (int mt = 0; mt < 2; mt++) {
        const int p0  = w * 32 + mt * 16 + prA;
        const int pyA = p0 >> 6;
        const int pxA = p0 & 63;
        laneA[mt] = (unsigned)((pyA * 66 + pxA) * 24 + 8 * k8A) * 2u;
    }
    const int hi8 = (t4 >= 2) ? 8 : 0;
    laneB = (unsigned)((hi8 + r8) * 152 + 8 * (t4 & 1)) * 2u;
}

// ---------------- kernel A: conv_x half -> partial ----------------

__global__ __launch_bounds__(256, 2)
void conv_x_half(int t)
{
    extern __shared__ __nv_bfloat16 smem[];
    const unsigned sIn0 = (unsigned)__cvta_generic_to_shared(smem);
    const unsigned sIn1 = sIn0 + INBUF_ELEMS * 2;
    const unsigned sW   = sIn0 + 2 * INBUF_ELEMS * 2;

    const int tid  = threadIdx.x;
    const int w    = tid >> 5;
    const int lane = tid & 31;
    const int y0   = blockIdx.x * 4;
    const int hcg  = blockIdx.y;
    const int b    = blockIdx.z;

    unsigned laneA[2], laneB;
    lane_setup(w, lane, laneA, laneB);

    float acc[2][8][4];
#pragma unroll
    for (int m = 0; m < 2; m++)
#pragma unroll
        for (int i = 0; i < 8; i++)
#pragma unroll
            for (int j = 0; j < 4; j++) acc[m][i][j] = 0.f;

    conv_half<0>(acc, t, y0, hcg, b, w, lane, tid, sIn0, sIn1, sW, laneA, laneB);

    // write partial, coalesced: index = ((slot*16 + q)*256 + tid)
    const int slot = ((int)blockIdx.x * 4 + hcg) * 8 + b;
    float4* dst = g_part[t];
#pragma unroll
    for (int m = 0; m < 2; m++)
#pragma unroll
        for (int i = 0; i < 8; i++) {
            float4 v;
            v.x = acc[m][i][0]; v.y = acc[m][i][1];
            v.z = acc[m][i][2]; v.w = acc[m][i][3];
            dst[((size_t)slot * 16 + (m * 8 + i)) * 256 + tid] = v;
        }
}

// ---------------- kernel B: conv_h half + LSTM epilogue ----------------

__global__ __launch_bounds__(256, 2)
void conv_h_half(float* __restrict__ hid_out, float* __restrict__ cell_io,
                 int t, int last)
{
    extern __shared__ __nv_bfloat16 smem[];
    const unsigned sIn0 = (unsigned)__cvta_generic_to_shared(smem);
    const unsigned sIn1 = sIn0 + INBUF_ELEMS * 2;
    const unsigned sW   = sIn0 + 2 * INBUF_ELEMS * 2;

    const int tid  = threadIdx.x;
    const int w    = tid >> 5;
    const int lane = tid & 31;
    const int y0   = blockIdx.x * 4;
    const int hcg  = blockIdx.y;
    const int b    = blockIdx.z;
    const int par_out = (t + 1) & 1;

    unsigned laneA[2], laneB;
    lane_setup(w, lane, laneA, laneB);

    // acc init from partial
    const int slot = ((int)blockIdx.x * 4 + hcg) * 8 + b;
    const float4* srcp = g_part[t];
    float acc[2][8][4];
#pragma unroll
    for (int m = 0; m < 2; m++)
#pragma unroll
        for (int i = 0; i < 8; i++) {
            float4 v = srcp[((size_t)slot * 16 + (m * 8 + i)) * 256 + tid];
            acc[m][i][0] = v.x; acc[m][i][1] = v.y;
            acc[m][i][2] = v.z; acc[m][i][3] = v.w;
        }

    if (t > 0)
        conv_half<1>(acc, t, y0, hcg, b, w, lane, tid, sIn0, sIn1, sW, laneA, laneB);

    // ---- fused LSTM epilogue ----
    const int c0    = (lane & 3) * 2;
    const int rbase = lane >> 2;
#pragma unroll
    for (int mt = 0; mt < 2; mt++) {
#pragma unroll
        for (int rr = 0; rr < 2; rr++) {
            const int pe = w * 32 + mt * 16 + rbase + 8 * rr;
            const int y  = y0 + (pe >> 6);
            const int x  = pe & 63;
#pragma unroll
            for (int q = 0; q < 4; q++) {
                const int hcl  = c0 + (q & 1) + ((q >> 1) << 3);
                const int off2 = (hcl >= 8) ? 1 : 0;
                const int cidx = (hcl & 7) - c0 + rr * 2;
                float vi = acc[mt][0 + off2][cidx];
                float vf = acc[mt][2 + off2][cidx];
                float vo = acc[mt][4 + off2][cidx];
                float vg = acc[mt][6 + off2][cidx];
                float iv = 1.f / (1.f + __expf(-vi));
                float fv = 1.f / (1.f + __expf(-vf));
                float ov = 1.f / (1.f + __expf(-vo));
                float gv = tanhf(vg);
                const int hc = hcg * 16 + hcl;
                const size_t addr = (((size_t)b * 64 + hc) * 64 + y) * 64 + x;
                float cold = (t == 0) ? 0.f : cell_io[addr];
                float cnew = fv * cold + iv * gv;
                cell_io[addr] = cnew;
                float hval = ov * tanhf(cnew);
                if (last) {
                    hid_out[addr] = hval;
                } else {
                    __nv_bfloat16 hh = __float2bfloat16(hval);
                    g_hs[par_out][0][b][y][x][hc] = hh;
                    g_hs[par_out][1][b][y][x][hc] =
                        __float2bfloat16(hval - __bfloat162float(hh));
                }
            }
        }
    }
}

// ---------------- host: streams/events (created pre-main) ----------------

static cudaStream_t g_s1 = 0;
static cudaEvent_t  g_fork = 0, g_ea[16];
static bool g_streams_ok = false;

struct StreamInit {
    StreamInit() {
        int lo = 0, hi = 0;
        if (cudaDeviceGetStreamPriorityRange(&lo, &hi) != cudaSuccess) return;
        if (cudaStreamCreateWithPriority(&g_s1, cudaStreamNonBlocking, lo)
            != cudaSuccess) return;                 // lo = least priority
        if (cudaEventCreateWithFlags(&g_fork, cudaEventDisableTiming)
            != cudaSuccess) return;
        for (int i = 0; i < 16; i++)
            if (cudaEventCreateWithFlags(&g_ea[i], cudaEventDisableTiming)
                != cudaSuccess) return;
        g_streams_ok = true;
    }
};
static StreamInit g_stream_init;

extern "C" void kernel_launch(void* const* d_in, const int* in_sizes, int n_in,
                              void* d_out, int out_size)
{
    const float* x  = (const float*)d_in[0];
    const float* Wk = (const float*)d_in[1];
    float* out  = (float*)d_out;
    float* hid  = out;
    float* cell = out + out_size / 2;

    static bool attr_done = false;
    if (!attr_done) {
        cudaFuncSetAttribute(conv_x_half,
                             cudaFuncAttributeMaxDynamicSharedMemorySize, SMEM_BYTES);
        cudaFuncSetAttribute(conv_h_half,
                             cudaFuncAttributeMaxDynamicSharedMemorySize, SMEM_BYTES);
        attr_done = true;
    }

    prep_wpk<<<(4 * 8 * 19456 + 255) / 256, 256>>>(Wk);
    prep_x<<<8 * 16 * 64, 256>>>(x);

    dim3 grid(16, 4, 8), blk(256);

    if (g_streams_ok) {
        // fork A-stream off the (captured) default stream
        cudaEventRecord(g_fork, 0);
        cudaStreamWaitEvent(g_s1, g_fork, 0);
        for (int t = 0; t < 16; t++) {
            conv_x_half<<<grid, blk, SMEM_BYTES, g_s1>>>(t);
            cudaEventRecord(g_ea[t], g_s1);
        }
        for (int t = 0; t < 16; t++) {
            cudaStreamWaitEvent(0, g_ea[t], 0);     // join A(t) -> B(t)
            conv_h_half<<<grid, blk, SMEM_BYTES>>>(hid, cell, t, t == 15 ? 1 : 0);
        }
    } else {
        // serial fallback (single stream), still correct
        for (int t = 0; t < 16; t++) {
            conv_x_half<<<grid, blk, SMEM_BYTES>>>(t);
            conv_h_half<<<grid, blk, SMEM_BYTES>>>(hid, cell, t, t == 15 ? 1 : 0);
        }
    }
}